// round 1
// baseline (speedup 1.0000x reference)
#include <cuda_runtime.h>
#include <math.h>

#define N_  32
#define D_  512
#define P_  4096
#define K_  64
#define EPSF 1e-12f

// ---------------- scratch (device globals; no allocation allowed) ----------
__device__ float g_invn[N_ * P_];                       // 512 KB
__device__ float g_a[(size_t)N_ * K_ * P_];             // 32 MB
__device__ float g_asum[N_ * K_];
__device__ float g_vlad[(size_t)N_ * K_ * D_];          // 4 MB
__device__ float g_gnorm2[N_];

// ---------------- k0: zero scratch -----------------------------------------
__global__ void k0_zero() {
    int i = blockIdx.x * 256 + threadIdx.x;
    if (i < N_ * K_ * D_) g_vlad[i] = 0.f;
    if (i < N_ * K_)      g_asum[i] = 0.f;
    if (i < N_)           g_gnorm2[i] = 0.f;
}

// ---------------- k1: per-pixel inverse L2 norm over channels --------------
__global__ void k1_invnorm(const float* __restrict__ x) {
    int idx = blockIdx.x * 256 + threadIdx.x;   // over N_*P_
    int n = idx >> 12;                          // P_ = 4096
    int p = idx & (P_ - 1);
    const float* xp = x + (size_t)n * D_ * P_ + p;
    float s = 0.f;
    #pragma unroll 8
    for (int d = 0; d < D_; d++) {
        float v = xp[(size_t)d * P_];
        s += v * v;
    }
    g_invn[idx] = 1.0f / fmaxf(sqrtf(s), EPSF);
}

// ---------------- k2: logits GEMM + softmax + a + asum ---------------------
// per block: one n, 128 pixels. logits[64,128] = W[64,512] @ X[512,128],
// scaled by invnorm, softmax over the 64 clusters, write a, accumulate asum.
__global__ __launch_bounds__(128) void k2_logits_softmax(
        const float* __restrict__ x, const float* __restrict__ w) {
    const int n  = blockIdx.y;
    const int p0 = blockIdx.x * 128;
    const int tid = threadIdx.x;

    __shared__ float As[16][64];       // W tile, transposed: As[kk][m]
    __shared__ float Bs[16][128];      // X tile: Bs[kk][pp]
    __shared__ float Ls[64][129];      // logits / a buffer (pad 1)

    const int tm = tid >> 4;           // 0..7   (cluster group)
    const int tn = tid & 15;           // 0..15  (pixel group)

    float acc[8][8];
    #pragma unroll
    for (int i = 0; i < 8; i++)
        #pragma unroll
        for (int j = 0; j < 8; j++) acc[i][j] = 0.f;

    const float* xn = x + (size_t)n * D_ * P_;

    for (int d0 = 0; d0 < D_; d0 += 16) {
        // W tile: As[kk][m] = w[m*512 + d0 + kk]
        {
            int m   = tid >> 1;
            int kk0 = (tid & 1) * 8;
            const float4* src = (const float4*)(w + m * D_ + d0 + kk0);
            float4 v0 = src[0], v1 = src[1];
            As[kk0 + 0][m] = v0.x; As[kk0 + 1][m] = v0.y;
            As[kk0 + 2][m] = v0.z; As[kk0 + 3][m] = v0.w;
            As[kk0 + 4][m] = v1.x; As[kk0 + 5][m] = v1.y;
            As[kk0 + 6][m] = v1.z; As[kk0 + 7][m] = v1.w;
        }
        // X tile: Bs[kk][pp] = x[n, d0+kk, p0+pp]   (coalesced float4 rows)
        {
            int c4 = tid & 31;
            int r0 = tid >> 5;
            #pragma unroll
            for (int rr = 0; rr < 4; rr++) {
                int kk = r0 + rr * 4;
                float4 v = *(const float4*)(xn + (size_t)(d0 + kk) * P_ + p0 + c4 * 4);
                *(float4*)(&Bs[kk][c4 * 4]) = v;
            }
        }
        __syncthreads();
        #pragma unroll
        for (int kk = 0; kk < 16; kk++) {
            float ra[8], rb[8];
            *(float4*)(ra)     = *(const float4*)(&As[kk][tm * 8]);
            *(float4*)(ra + 4) = *(const float4*)(&As[kk][tm * 8 + 4]);
            *(float4*)(rb)     = *(const float4*)(&Bs[kk][tn * 8]);
            *(float4*)(rb + 4) = *(const float4*)(&Bs[kk][tn * 8 + 4]);
            #pragma unroll
            for (int i = 0; i < 8; i++)
                #pragma unroll
                for (int j = 0; j < 8; j++)
                    acc[i][j] += ra[i] * rb[j];
        }
        __syncthreads();
    }

    // scale by per-pixel invnorm, stage logits to smem
    float invn[8];
    #pragma unroll
    for (int j = 0; j < 8; j++) invn[j] = g_invn[n * P_ + p0 + tn * 8 + j];
    #pragma unroll
    for (int i = 0; i < 8; i++)
        #pragma unroll
        for (int j = 0; j < 8; j++)
            Ls[tm * 8 + i][tn * 8 + j] = acc[i][j] * invn[j];
    __syncthreads();

    // softmax over clusters; one thread per pixel column
    {
        float m = -1e30f;
        for (int k = 0; k < 64; k++) m = fmaxf(m, Ls[k][tid]);
        float s = 0.f;
        for (int k = 0; k < 64; k++) {
            float e = expf(Ls[k][tid] - m);
            Ls[k][tid] = e;
            s += e;
        }
        float inv = 1.0f / s;
        for (int k = 0; k < 64; k++) Ls[k][tid] *= inv;
    }
    __syncthreads();

    // write a (coalesced per cluster row)
    float* an = g_a + (size_t)n * K_ * P_ + p0;
    for (int k = 0; k < 64; k++) an[(size_t)k * P_ + tid] = Ls[k][tid];

    // asum: one thread per cluster
    if (tid < 64) {
        float s = 0.f;
        for (int p = 0; p < 128; p++) s += Ls[tid][p];
        atomicAdd(&g_asum[n * K_ + tid], s);
    }
}

// ---------------- k3: vlad GEMM (split-P, atomic epilogue) -----------------
// vlad[n,k,d] += sum_p (a[n,k,p]*invn[n,p]) * x[n,d,p]  over this p-chunk
__global__ __launch_bounds__(128) void k3_vlad(const float* __restrict__ x) {
    const int n  = blockIdx.z;
    const int pc = blockIdx.y;               // p-chunk (4 of 1024)
    const int d0 = blockIdx.x * 128;
    const int tid = threadIdx.x;
    const int pbase = pc * (P_ / 4);

    __shared__ float As[16][64];              // a*invn, transposed: As[pp][m]
    __shared__ float Bs[16][132];             // x, transposed: Bs[pp][dd]
    __shared__ float invs[P_ / 4];            // 1024 floats

    for (int i = tid; i < P_ / 4; i += 128) invs[i] = g_invn[n * P_ + pbase + i];
    __syncthreads();

    const int tm = tid >> 4, tn = tid & 15;
    float acc[8][8];
    #pragma unroll
    for (int i = 0; i < 8; i++)
        #pragma unroll
        for (int j = 0; j < 8; j++) acc[i][j] = 0.f;

    const float* xn = x + (size_t)n * D_ * P_;
    const float* an = g_a + (size_t)n * K_ * P_;

    for (int pp0 = 0; pp0 < P_ / 4; pp0 += 16) {
        // a tile
        {
            int m  = tid >> 1;
            int q0 = (tid & 1) * 8;
            const float4* src = (const float4*)(an + (size_t)m * P_ + pbase + pp0 + q0);
            float4 v0 = src[0], v1 = src[1];
            As[q0 + 0][m] = v0.x * invs[pp0 + q0 + 0];
            As[q0 + 1][m] = v0.y * invs[pp0 + q0 + 1];
            As[q0 + 2][m] = v0.z * invs[pp0 + q0 + 2];
            As[q0 + 3][m] = v0.w * invs[pp0 + q0 + 3];
            As[q0 + 4][m] = v1.x * invs[pp0 + q0 + 4];
            As[q0 + 5][m] = v1.y * invs[pp0 + q0 + 5];
            As[q0 + 6][m] = v1.z * invs[pp0 + q0 + 6];
            As[q0 + 7][m] = v1.w * invs[pp0 + q0 + 7];
        }
        // x tile: each thread one d-row, 16 p values, transpose on store
        {
            const float4* src = (const float4*)(xn + (size_t)(d0 + tid) * P_ + pbase + pp0);
            float4 v0 = src[0], v1 = src[1], v2 = src[2], v3 = src[3];
            Bs[ 0][tid] = v0.x; Bs[ 1][tid] = v0.y; Bs[ 2][tid] = v0.z; Bs[ 3][tid] = v0.w;
            Bs[ 4][tid] = v1.x; Bs[ 5][tid] = v1.y; Bs[ 6][tid] = v1.z; Bs[ 7][tid] = v1.w;
            Bs[ 8][tid] = v2.x; Bs[ 9][tid] = v2.y; Bs[10][tid] = v2.z; Bs[11][tid] = v2.w;
            Bs[12][tid] = v3.x; Bs[13][tid] = v3.y; Bs[14][tid] = v3.z; Bs[15][tid] = v3.w;
        }
        __syncthreads();
        #pragma unroll
        for (int kk = 0; kk < 16; kk++) {
            float ra[8], rb[8];
            *(float4*)(ra)     = *(const float4*)(&As[kk][tm * 8]);
            *(float4*)(ra + 4) = *(const float4*)(&As[kk][tm * 8 + 4]);
            *(float4*)(rb)     = *(const float4*)(&Bs[kk][tn * 8]);
            *(float4*)(rb + 4) = *(const float4*)(&Bs[kk][tn * 8 + 4]);
            #pragma unroll
            for (int i = 0; i < 8; i++)
                #pragma unroll
                for (int j = 0; j < 8; j++)
                    acc[i][j] += ra[i] * rb[j];
        }
        __syncthreads();
    }

    float* vl = g_vlad + (size_t)n * K_ * D_ + d0;
    #pragma unroll
    for (int i = 0; i < 8; i++)
        #pragma unroll
        for (int j = 0; j < 8; j++)
            atomicAdd(&vl[(size_t)(tm * 8 + i) * D_ + tn * 8 + j], acc[i][j]);
}

// ---------------- k4a: subtract centroid term, intra-normalize -------------
__global__ __launch_bounds__(128) void k4a_finalize(
        const float* __restrict__ cent, float* __restrict__ out) {
    const int k = blockIdx.x, n = blockIdx.y;
    const int tid = threadIdx.x;
    const float asum = g_asum[n * K_ + k];
    const float* vl = g_vlad + ((size_t)n * K_ + k) * D_;
    const float* ck = cent + (size_t)k * D_;

    float t[4];
    float s2 = 0.f;
    #pragma unroll
    for (int r = 0; r < 4; r++) {
        int d = r * 128 + tid;
        t[r] = vl[d] - asum * ck[d];
        s2 += t[r] * t[r];
    }
    #pragma unroll
    for (int o = 16; o > 0; o >>= 1) s2 += __shfl_xor_sync(0xffffffffu, s2, o);
    __shared__ float red[4];
    if ((tid & 31) == 0) red[tid >> 5] = s2;
    __syncthreads();
    float total = red[0] + red[1] + red[2] + red[3];
    float inv = 1.0f / fmaxf(sqrtf(total), EPSF);

    float* o = out + ((size_t)n * K_ + k) * D_;
    #pragma unroll
    for (int r = 0; r < 4; r++) o[r * 128 + tid] = t[r] * inv;
    if (tid == 0) atomicAdd(&g_gnorm2[n], total * inv * inv);
}

// ---------------- k4b: global L2 scale --------------------------------------
__global__ void k4b_global(float* __restrict__ out) {
    int i = blockIdx.x * 256 + threadIdx.x;       // N_*K_*D_
    int n = i >> 15;                               // K_*D_ = 32768
    float inv = 1.0f / fmaxf(sqrtf(g_gnorm2[n]), EPSF);
    out[i] *= inv;
}

// ---------------- launch -----------------------------------------------------
extern "C" void kernel_launch(void* const* d_in, const int* in_sizes, int n_in,
                              void* d_out, int out_size) {
    const float* x = (const float*)d_in[0];   // [32, 512, 64, 64]
    const float* w = (const float*)d_in[1];   // [64, 512]
    const float* c = (const float*)d_in[2];   // [64, 512]
    float* out = (float*)d_out;               // [32, 32768]

    k0_zero<<<(N_ * K_ * D_ + 255) / 256, 256>>>();
    k1_invnorm<<<(N_ * P_) / 256, 256>>>(x);

    dim3 g2(P_ / 128, N_);
    k2_logits_softmax<<<g2, 128>>>(x, w);

    dim3 g3(D_ / 128, 4, N_);
    k3_vlad<<<g3, 128>>>(x);

    dim3 g4(K_, N_);
    k4a_finalize<<<g4, 128>>>(c, out);

    k4b_global<<<(N_ * K_ * D_) / 256, 256>>>(out);
}

// round 3
// speedup vs baseline: 1.8832x; 1.8832x over previous
#include <cuda_runtime.h>
#include <cuda_bf16.h>
#include <math.h>
#include <stdint.h>

#define N_  32
#define D_  512
#define P_  4096
#define K_  64
#define EPSF 1e-12f

// ---------------- scratch (device globals) ----------------------------------
__device__ float g_invn[N_ * P_];
__device__ float g_a[(size_t)N_ * K_ * P_];             // 32 MB
__device__ float g_asum[N_ * K_];
__device__ float g_vlad[(size_t)N_ * K_ * D_];          // 4 MB
__device__ float g_gnorm2[N_];

// ---------------- helpers ----------------------------------------------------
__device__ __forceinline__ void mma_bf16(float* c, const uint32_t* a, const uint32_t* b) {
    asm volatile(
        "mma.sync.aligned.m16n8k16.row.col.f32.bf16.bf16.f32 "
        "{%0,%1,%2,%3}, {%4,%5,%6,%7}, {%8,%9}, {%0,%1,%2,%3};"
        : "+f"(c[0]), "+f"(c[1]), "+f"(c[2]), "+f"(c[3])
        : "r"(a[0]), "r"(a[1]), "r"(a[2]), "r"(a[3]), "r"(b[0]), "r"(b[1]));
}
__device__ __forceinline__ uint32_t pack2(float a, float b) {
    __nv_bfloat162 h = __floats2bfloat162_rn(a, b);
    return *(uint32_t*)&h;
}
__device__ __forceinline__ float bf_hi(float v) {
    return __bfloat162float(__float2bfloat16_rn(v));
}
// split a float4 into bf16 hi (rn) and bf16 lo (residual)
__device__ __forceinline__ void split4(float4 v, uint2& h, uint2& l) {
    float hx = bf_hi(v.x), hy = bf_hi(v.y), hz = bf_hi(v.z), hw = bf_hi(v.w);
    h.x = pack2(v.x, v.y);           h.y = pack2(v.z, v.w);
    l.x = pack2(v.x - hx, v.y - hy); l.y = pack2(v.z - hz, v.w - hw);
}

// ---------------- k0: zero asum/gnorm ----------------------------------------
__global__ void k0_zero() {
    int i = blockIdx.x * 256 + threadIdx.x;
    if (i < N_ * K_) g_asum[i] = 0.f;
    if (i < N_)      g_gnorm2[i] = 0.f;
}

// ---------------- k1: per-pixel inverse L2 norm -------------------------------
__global__ void k1_invnorm(const float* __restrict__ x) {
    int idx = blockIdx.x * 256 + threadIdx.x;
    int n = idx >> 12;
    int p = idx & (P_ - 1);
    const float* xp = x + (size_t)n * D_ * P_ + p;
    float s = 0.f;
    #pragma unroll 8
    for (int d = 0; d < D_; d++) {
        float v = xp[(size_t)d * P_];
        s += v * v;
    }
    g_invn[idx] = 1.0f / fmaxf(sqrtf(s), EPSF);
}

// ---------------- k2: logits GEMM (mma.sync) + softmax + a + asum -------------
// block = (n, 128 pixels), 128 threads (4 warps).
// logits[64 k, 128 p] = W[64,512] @ X[512,128], scaled by invn, softmax over k.
#define ST2 40                                  // bf16 row stride for 32-wide tiles
#define K2_SMEM (64*132*4 + 128*4 + (64*ST2*2 + 128*ST2*2) * 2)

__global__ __launch_bounds__(128) void k2_mma(
        const float* __restrict__ x, const float* __restrict__ wgt) {
    extern __shared__ char sm2[];
    float* Ls = (float*)sm2;                                   // [64][132]
    float* sInv = Ls + 64 * 132;                               // [128]
    __nv_bfloat16* Wh = (__nv_bfloat16*)(sInv + 128);          // [64][ST2]
    __nv_bfloat16* Wl = Wh + 64 * ST2;
    __nv_bfloat16* Th = Wl + 64 * ST2;                         // xT [128][ST2]
    __nv_bfloat16* Tl = Th + 128 * ST2;

    const int n  = blockIdx.y;
    const int p0 = blockIdx.x * 128;
    const int tid = threadIdx.x;
    const int w = tid >> 5, lane = tid & 31;
    const int g = lane >> 2, tc = lane & 3;

    sInv[tid] = g_invn[n * P_ + p0 + tid];

    float acc[4][4][4];
    #pragma unroll
    for (int i = 0; i < 4; i++)
        #pragma unroll
        for (int j = 0; j < 4; j++)
            #pragma unroll
            for (int q = 0; q < 4; q++) acc[i][j][q] = 0.f;

    const float* xb = x + (size_t)n * D_ * P_ + p0 + tid;   // this thread's pixel column

    for (int dc = 0; dc < 16; dc++) {
        const int d0 = dc * 32;
        __syncthreads();
        // stage W chunk [64 x 32] hi/lo
        {
            int k = tid >> 1, off = (tid & 1) * 16;
            const float4* src = (const float4*)(wgt + k * D_ + d0 + off);
            #pragma unroll
            for (int q = 0; q < 4; q++) {
                float4 v = src[q];
                uint2 h, l; split4(v, h, l);
                *(uint2*)(Wh + k * ST2 + off + q * 4) = h;
                *(uint2*)(Wl + k * ST2 + off + q * 4) = l;
            }
        }
        // stage xT chunk [128 p][32 d] hi/lo (one pixel per thread)
        {
            #pragma unroll
            for (int dd = 0; dd < 32; dd += 4) {
                float v0 = xb[(size_t)(d0 + dd + 0) * P_];
                float v1 = xb[(size_t)(d0 + dd + 1) * P_];
                float v2 = xb[(size_t)(d0 + dd + 2) * P_];
                float v3 = xb[(size_t)(d0 + dd + 3) * P_];
                float4 v = {v0, v1, v2, v3};
                uint2 h, l; split4(v, h, l);
                *(uint2*)(Th + tid * ST2 + dd) = h;
                *(uint2*)(Tl + tid * ST2 + dd) = l;
            }
        }
        __syncthreads();
        #pragma unroll
        for (int ks = 0; ks < 2; ks++) {
            const int kb = ks * 16;
            uint32_t Bh[4][2], Bl[4][2];
            #pragma unroll
            for (int t = 0; t < 4; t++) {
                int col = w * 32 + t * 8 + g;
                Bh[t][0] = *(const uint32_t*)(Th + col * ST2 + kb + tc * 2);
                Bh[t][1] = *(const uint32_t*)(Th + col * ST2 + kb + 8 + tc * 2);
                Bl[t][0] = *(const uint32_t*)(Tl + col * ST2 + kb + tc * 2);
                Bl[t][1] = *(const uint32_t*)(Tl + col * ST2 + kb + 8 + tc * 2);
            }
            #pragma unroll
            for (int mt = 0; mt < 4; mt++) {
                const int ar = mt * 16 + g;
                uint32_t Ah[4], Al[4];
                Ah[0] = *(const uint32_t*)(Wh + ar * ST2 + kb + tc * 2);
                Ah[1] = *(const uint32_t*)(Wh + (ar + 8) * ST2 + kb + tc * 2);
                Ah[2] = *(const uint32_t*)(Wh + ar * ST2 + kb + 8 + tc * 2);
                Ah[3] = *(const uint32_t*)(Wh + (ar + 8) * ST2 + kb + 8 + tc * 2);
                Al[0] = *(const uint32_t*)(Wl + ar * ST2 + kb + tc * 2);
                Al[1] = *(const uint32_t*)(Wl + (ar + 8) * ST2 + kb + tc * 2);
                Al[2] = *(const uint32_t*)(Wl + ar * ST2 + kb + 8 + tc * 2);
                Al[3] = *(const uint32_t*)(Wl + (ar + 8) * ST2 + kb + 8 + tc * 2);
                #pragma unroll
                for (int t = 0; t < 4; t++) {
                    mma_bf16(acc[mt][t], Ah, Bh[t]);
                    mma_bf16(acc[mt][t], Ah, Bl[t]);
                    mma_bf16(acc[mt][t], Al, Bh[t]);
                }
            }
        }
    }
    __syncthreads();

    // epilogue: scale by invn, stage logits into Ls
    #pragma unroll
    for (int mt = 0; mt < 4; mt++)
        #pragma unroll
        for (int t = 0; t < 4; t++) {
            int col = w * 32 + t * 8 + tc * 2;
            int row = mt * 16 + g;
            Ls[row * 132 + col]           = acc[mt][t][0] * sInv[col];
            Ls[row * 132 + col + 1]       = acc[mt][t][1] * sInv[col + 1];
            Ls[(row + 8) * 132 + col]     = acc[mt][t][2] * sInv[col];
            Ls[(row + 8) * 132 + col + 1] = acc[mt][t][3] * sInv[col + 1];
        }
    __syncthreads();

    // softmax over clusters; one thread per pixel column
    {
        float m = -1e30f;
        for (int k = 0; k < 64; k++) m = fmaxf(m, Ls[k * 132 + tid]);
        float s = 0.f;
        for (int k = 0; k < 64; k++) {
            float e = expf(Ls[k * 132 + tid] - m);
            Ls[k * 132 + tid] = e;
            s += e;
        }
        float inv = 1.0f / s;
        for (int k = 0; k < 64; k++) Ls[k * 132 + tid] *= inv;
    }
    __syncthreads();

    float* an = g_a + (size_t)n * K_ * P_ + p0;
    for (int k = 0; k < 64; k++) an[(size_t)k * P_ + tid] = Ls[k * 132 + tid];

    if (tid < 64) {
        float s = 0.f;
        for (int p = 0; p < 128; p++) s += Ls[tid * 132 + p];
        atomicAdd(&g_asum[n * K_ + tid], s);
    }
}

// ---------------- k3: vlad GEMM (mma.sync, bf16 3-split) ----------------------
// block = (n, 128-d chunk), 512 threads (16 warps).
// vladT[128 d, 64 k] = X[d, p] * Aeff[k, p]^T   over p = 0..4095
#define ST3 136
#define K3_SMEM ((128 * ST3 * 2 + 64 * ST3 * 2) * 2)   // 104448 bytes

__global__ __launch_bounds__(512) void k3_mma(const float* __restrict__ x) {
    extern __shared__ char sm3[];
    __nv_bfloat16* Xh = (__nv_bfloat16*)sm3;            // [128][ST3]
    __nv_bfloat16* Xl = Xh + 128 * ST3;
    __nv_bfloat16* Ahs = Xl + 128 * ST3;                // [64][ST3]
    __nv_bfloat16* Als = Ahs + 64 * ST3;

    const int n  = blockIdx.y;
    const int d0 = blockIdx.x * 128;
    const int tid = threadIdx.x;
    const int w = tid >> 5, lane = tid & 31;
    const int g = lane >> 2, tc = lane & 3;
    const int mt = w >> 1;                 // 0..7
    const int nh = (w & 1) * 32;           // column half

    const float* xn = x + (size_t)n * D_ * P_ + (size_t)d0 * P_;
    const float* an = g_a + (size_t)n * K_ * P_;

    float acc[4][4];
    #pragma unroll
    for (int t = 0; t < 4; t++)
        #pragma unroll
        for (int q = 0; q < 4; q++) acc[t][q] = 0.f;

    const int c4 = tid & 31;      // p-group (4 pixels)
    const int r0 = tid >> 5;      // 0..15

    for (int pc = 0; pc < P_ / 128; pc++) {
        const int pbase = pc * 128;
        __syncthreads();
        float4 iv = *(const float4*)(g_invn + n * P_ + pbase + c4 * 4);
        // stage X [128 d][128 p] hi/lo
        #pragma unroll
        for (int rr = 0; rr < 8; rr++) {
            int row = r0 + rr * 16;
            float4 v = *(const float4*)(xn + (size_t)row * P_ + pbase + c4 * 4);
            uint2 h, l; split4(v, h, l);
            *(uint2*)(Xh + row * ST3 + c4 * 4) = h;
            *(uint2*)(Xl + row * ST3 + c4 * 4) = l;
        }
        // stage Aeff [64 k][128 p] hi/lo (fold invn)
        #pragma unroll
        for (int rr = 0; rr < 4; rr++) {
            int row = r0 + rr * 16;
            float4 v = *(const float4*)(an + (size_t)row * P_ + pbase + c4 * 4);
            v.x *= iv.x; v.y *= iv.y; v.z *= iv.z; v.w *= iv.w;
            uint2 h, l; split4(v, h, l);
            *(uint2*)(Ahs + row * ST3 + c4 * 4) = h;
            *(uint2*)(Als + row * ST3 + c4 * 4) = l;
        }
        __syncthreads();
        #pragma unroll
        for (int ks = 0; ks < 8; ks++) {
            const int kb = ks * 16;
            uint32_t Bh[4][2], Bl[4][2];
            #pragma unroll
            for (int t = 0; t < 4; t++) {
                int col = nh + t * 8 + g;
                Bh[t][0] = *(const uint32_t*)(Ahs + col * ST3 + kb + tc * 2);
                Bh[t][1] = *(const uint32_t*)(Ahs + col * ST3 + kb + 8 + tc * 2);
                Bl[t][0] = *(const uint32_t*)(Als + col * ST3 + kb + tc * 2);
                Bl[t][1] = *(const uint32_t*)(Als + col * ST3 + kb + 8 + tc * 2);
            }
            const int ar = mt * 16 + g;
            uint32_t Ah[4], Al[4];
            Ah[0] = *(const uint32_t*)(Xh + ar * ST3 + kb + tc * 2);
            Ah[1] = *(const uint32_t*)(Xh + (ar + 8) * ST3 + kb + tc * 2);
            Ah[2] = *(const uint32_t*)(Xh + ar * ST3 + kb + 8 + tc * 2);
            Ah[3] = *(const uint32_t*)(Xh + (ar + 8) * ST3 + kb + 8 + tc * 2);
            Al[0] = *(const uint32_t*)(Xl + ar * ST3 + kb + tc * 2);
            Al[1] = *(const uint32_t*)(Xl + (ar + 8) * ST3 + kb + tc * 2);
            Al[2] = *(const uint32_t*)(Xl + ar * ST3 + kb + 8 + tc * 2);
            Al[3] = *(const uint32_t*)(Xl + (ar + 8) * ST3 + kb + 8 + tc * 2);
            #pragma unroll
            for (int t = 0; t < 4; t++) {
                mma_bf16(acc[t], Ah, Bh[t]);
                mma_bf16(acc[t], Ah, Bl[t]);
                mma_bf16(acc[t], Al, Bh[t]);
            }
        }
    }

    // epilogue: acc (row=d_local, col=k) -> g_vlad[n][k][d]
    float* vb = g_vlad + (size_t)n * K_ * D_ + d0;
    const int r = mt * 16 + g;
    #pragma unroll
    for (int t = 0; t < 4; t++) {
        int kc = nh + t * 8 + tc * 2;
        vb[(size_t)kc * D_ + r]           = acc[t][0];
        vb[(size_t)(kc + 1) * D_ + r]     = acc[t][1];
        vb[(size_t)kc * D_ + r + 8]       = acc[t][2];
        vb[(size_t)(kc + 1) * D_ + r + 8] = acc[t][3];
    }
}

// ---------------- k4a: centroid subtraction + intra-normalize -----------------
__global__ __launch_bounds__(128) void k4a_finalize(
        const float* __restrict__ cent, float* __restrict__ out) {
    const int k = blockIdx.x, n = blockIdx.y;
    const int tid = threadIdx.x;
    const float asum = g_asum[n * K_ + k];
    const float* vl = g_vlad + ((size_t)n * K_ + k) * D_;
    const float* ck = cent + (size_t)k * D_;

    float t[4];
    float s2 = 0.f;
    #pragma unroll
    for (int r = 0; r < 4; r++) {
        int d = r * 128 + tid;
        t[r] = vl[d] - asum * ck[d];
        s2 += t[r] * t[r];
    }
    #pragma unroll
    for (int o = 16; o > 0; o >>= 1) s2 += __shfl_xor_sync(0xffffffffu, s2, o);
    __shared__ float red[4];
    if ((tid & 31) == 0) red[tid >> 5] = s2;
    __syncthreads();
    float total = red[0] + red[1] + red[2] + red[3];
    float inv = 1.0f / fmaxf(sqrtf(total), EPSF);

    float* o = out + ((size_t)n * K_ + k) * D_;
    #pragma unroll
    for (int r = 0; r < 4; r++) o[r * 128 + tid] = t[r] * inv;
    if (tid == 0) atomicAdd(&g_gnorm2[n], total * inv * inv);
}

// ---------------- k4b: global L2 scale -----------------------------------------
__global__ void k4b_global(float* __restrict__ out) {
    int i = blockIdx.x * 256 + threadIdx.x;
    int n = i >> 15;
    float inv = 1.0f / fmaxf(sqrtf(g_gnorm2[n]), EPSF);
    out[i] *= inv;
}

// ---------------- launch --------------------------------------------------------
extern "C" void kernel_launch(void* const* d_in, const int* in_sizes, int n_in,
                              void* d_out, int out_size) {
    const float* x = (const float*)d_in[0];
    const float* w = (const float*)d_in[1];
    const float* c = (const float*)d_in[2];
    float* out = (float*)d_out;

    static bool attr_done = false;
    if (!attr_done) {
        cudaFuncSetAttribute(k2_mma, cudaFuncAttributeMaxDynamicSharedMemorySize, K2_SMEM);
        cudaFuncSetAttribute(k3_mma, cudaFuncAttributeMaxDynamicSharedMemorySize, K3_SMEM);
        attr_done = true;
    }

    k0_zero<<<8, 256>>>();
    k1_invnorm<<<(N_ * P_) / 256, 256>>>(x);

    dim3 g2(P_ / 128, N_);
    k2_mma<<<g2, 128, K2_SMEM>>>(x, w);

    dim3 g3(D_ / 128, N_);
    k3_mma<<<g3, 512, K3_SMEM>>>(x);

    dim3 g4(K_, N_);
    k4a_finalize<<<g4, 128>>>(c, out);

    k4b_global<<<(N_ * K_ * D_) / 256, 256>>>(out);
}

// round 4
// speedup vs baseline: 2.3914x; 1.2698x over previous
#include <cuda_runtime.h>
#include <cuda_bf16.h>
#include <math.h>
#include <stdint.h>

#define N_  32
#define D_  512
#define P_  4096
#define K_  64
#define EPSF 1e-12f

// ---------------- scratch (device globals) ----------------------------------
__device__ __nv_bfloat16 g_ah[(size_t)N_ * K_ * P_];    // a*invn hi (16 MB)
__device__ __nv_bfloat16 g_al[(size_t)N_ * K_ * P_];    // a*invn lo (16 MB)
__device__ float g_asum[N_ * K_];
__device__ float g_vlad[(size_t)N_ * K_ * D_];          // 4 MB
__device__ float g_gnorm2[N_];

// ---------------- helpers ----------------------------------------------------
__device__ __forceinline__ uint32_t smem_u32(const void* p) {
    uint32_t a;
    asm("{ .reg .u64 t; cvta.to.shared.u64 t, %1; cvt.u32.u64 %0, t; }" : "=r"(a) : "l"(p));
    return a;
}
__device__ __forceinline__ void mma_bf16(float* c, const uint32_t* a, const uint32_t* b) {
    asm volatile(
        "mma.sync.aligned.m16n8k16.row.col.f32.bf16.bf16.f32 "
        "{%0,%1,%2,%3}, {%4,%5,%6,%7}, {%8,%9}, {%0,%1,%2,%3};"
        : "+f"(c[0]), "+f"(c[1]), "+f"(c[2]), "+f"(c[3])
        : "r"(a[0]), "r"(a[1]), "r"(a[2]), "r"(a[3]), "r"(b[0]), "r"(b[1]));
}
__device__ __forceinline__ uint32_t pack2(float a, float b) {
    __nv_bfloat162 h = __floats2bfloat162_rn(a, b);
    return *(uint32_t*)&h;
}
__device__ __forceinline__ float bf_hi(float v) {
    return __bfloat162float(__float2bfloat16_rn(v));
}
__device__ __forceinline__ void split4(float4 v, uint2& h, uint2& l) {
    float hx = bf_hi(v.x), hy = bf_hi(v.y), hz = bf_hi(v.z), hw = bf_hi(v.w);
    h.x = pack2(v.x, v.y);           h.y = pack2(v.z, v.w);
    l.x = pack2(v.x - hx, v.y - hy); l.y = pack2(v.z - hz, v.w - hw);
}
__device__ __forceinline__ void cp16(void* dst_smem, const void* src) {
    asm volatile("cp.async.cg.shared.global [%0], [%1], 16;"
                 :: "r"(smem_u32(dst_smem)), "l"(src) : "memory");
}
#define CP_COMMIT() asm volatile("cp.async.commit_group;" ::: "memory")
#define CP_WAIT0()  asm volatile("cp.async.wait_group 0;" ::: "memory")

// ---------------- k0: zero asum/gnorm ----------------------------------------
__global__ void k0_zero() {
    int i = blockIdx.x * 256 + threadIdx.x;
    if (i < N_ * K_) g_asum[i] = 0.f;
    if (i < N_)      g_gnorm2[i] = 0.f;
}

// ---------------- k2: fused norm + logits GEMM + softmax + a_eff + asum ------
// block = (n, 128 pixels), 128 threads (4 warps).
#define ST2 40
#define K2_SMEM (64*132*4 + 128*4 + (64*ST2*2 + 128*ST2*2) * 2)

__global__ __launch_bounds__(128) void k2_mma(
        const float* __restrict__ x, const float* __restrict__ wgt) {
    extern __shared__ char sm2[];
    float* Ls = (float*)sm2;                                   // [64][132]
    float* sInv = Ls + 64 * 132;                               // [128]
    __nv_bfloat16* Wh = (__nv_bfloat16*)(sInv + 128);          // [64][ST2]
    __nv_bfloat16* Wl = Wh + 64 * ST2;
    __nv_bfloat16* Th = Wl + 64 * ST2;                         // xT [128][ST2]
    __nv_bfloat16* Tl = Th + 128 * ST2;

    const int n  = blockIdx.y;
    const int p0 = blockIdx.x * 128;
    const int tid = threadIdx.x;
    const int w = tid >> 5, lane = tid & 31;
    const int g = lane >> 2, tc = lane & 3;

    float acc[4][4][4];
    #pragma unroll
    for (int i = 0; i < 4; i++)
        #pragma unroll
        for (int j = 0; j < 4; j++)
            #pragma unroll
            for (int q = 0; q < 4; q++) acc[i][j][q] = 0.f;

    const float* xb = x + (size_t)n * D_ * P_ + p0 + tid;   // this thread's pixel
    float ss = 0.f;                                          // per-pixel sum of squares

    for (int dc = 0; dc < 16; dc++) {
        const int d0 = dc * 32;
        __syncthreads();
        // stage W chunk [64 x 32] hi/lo
        {
            int k = tid >> 1, off = (tid & 1) * 16;
            const float4* src = (const float4*)(wgt + k * D_ + d0 + off);
            #pragma unroll
            for (int q = 0; q < 4; q++) {
                float4 v = src[q];
                uint2 h, l; split4(v, h, l);
                *(uint2*)(Wh + k * ST2 + off + q * 4) = h;
                *(uint2*)(Wl + k * ST2 + off + q * 4) = l;
            }
        }
        // stage xT chunk [128 p][32 d] hi/lo + accumulate ss
        {
            #pragma unroll
            for (int dd = 0; dd < 32; dd += 4) {
                float v0 = xb[(size_t)(d0 + dd + 0) * P_];
                float v1 = xb[(size_t)(d0 + dd + 1) * P_];
                float v2 = xb[(size_t)(d0 + dd + 2) * P_];
                float v3 = xb[(size_t)(d0 + dd + 3) * P_];
                ss += v0 * v0 + v1 * v1 + v2 * v2 + v3 * v3;
                float4 v = {v0, v1, v2, v3};
                uint2 h, l; split4(v, h, l);
                *(uint2*)(Th + tid * ST2 + dd) = h;
                *(uint2*)(Tl + tid * ST2 + dd) = l;
            }
        }
        __syncthreads();
        #pragma unroll
        for (int ks = 0; ks < 2; ks++) {
            const int kb = ks * 16;
            uint32_t Bh[4][2], Bl[4][2];
            #pragma unroll
            for (int t = 0; t < 4; t++) {
                int col = w * 32 + t * 8 + g;
                Bh[t][0] = *(const uint32_t*)(Th + col * ST2 + kb + tc * 2);
                Bh[t][1] = *(const uint32_t*)(Th + col * ST2 + kb + 8 + tc * 2);
                Bl[t][0] = *(const uint32_t*)(Tl + col * ST2 + kb + tc * 2);
                Bl[t][1] = *(const uint32_t*)(Tl + col * ST2 + kb + 8 + tc * 2);
            }
            #pragma unroll
            for (int mt = 0; mt < 4; mt++) {
                const int ar = mt * 16 + g;
                uint32_t Ah[4], Al[4];
                Ah[0] = *(const uint32_t*)(Wh + ar * ST2 + kb + tc * 2);
                Ah[1] = *(const uint32_t*)(Wh + (ar + 8) * ST2 + kb + tc * 2);
                Ah[2] = *(const uint32_t*)(Wh + ar * ST2 + kb + 8 + tc * 2);
                Ah[3] = *(const uint32_t*)(Wh + (ar + 8) * ST2 + kb + 8 + tc * 2);
                Al[0] = *(const uint32_t*)(Wl + ar * ST2 + kb + tc * 2);
                Al[1] = *(const uint32_t*)(Wl + (ar + 8) * ST2 + kb + tc * 2);
                Al[2] = *(const uint32_t*)(Wl + ar * ST2 + kb + 8 + tc * 2);
                Al[3] = *(const uint32_t*)(Wl + (ar + 8) * ST2 + kb + 8 + tc * 2);
                #pragma unroll
                for (int t = 0; t < 4; t++) {
                    mma_bf16(acc[mt][t], Ah, Bh[t]);
                    mma_bf16(acc[mt][t], Ah, Bl[t]);
                    mma_bf16(acc[mt][t], Al, Bh[t]);
                }
            }
        }
    }
    const float invnv = 1.0f / fmaxf(sqrtf(ss), EPSF);
    sInv[tid] = invnv;
    __syncthreads();

    // epilogue: scale by invn, stage logits into Ls
    #pragma unroll
    for (int mt = 0; mt < 4; mt++)
        #pragma unroll
        for (int t = 0; t < 4; t++) {
            int col = w * 32 + t * 8 + tc * 2;
            int row = mt * 16 + g;
            Ls[row * 132 + col]           = acc[mt][t][0] * sInv[col];
            Ls[row * 132 + col + 1]       = acc[mt][t][1] * sInv[col + 1];
            Ls[(row + 8) * 132 + col]     = acc[mt][t][2] * sInv[col];
            Ls[(row + 8) * 132 + col + 1] = acc[mt][t][3] * sInv[col + 1];
        }
    __syncthreads();

    // softmax over clusters; one thread per pixel column
    {
        float m = -1e30f;
        for (int k = 0; k < 64; k++) m = fmaxf(m, Ls[k * 132 + tid]);
        float s = 0.f;
        for (int k = 0; k < 64; k++) {
            float e = expf(Ls[k * 132 + tid] - m);
            Ls[k * 132 + tid] = e;
            s += e;
        }
        float inv = 1.0f / s;
        for (int k = 0; k < 64; k++) Ls[k * 132 + tid] *= inv;
    }
    __syncthreads();

    // write a_eff = a * invn, split bf16 hi/lo
    {
        __nv_bfloat16* ah = g_ah + (size_t)n * K_ * P_ + p0 + tid;
        __nv_bfloat16* al = g_al + (size_t)n * K_ * P_ + p0 + tid;
        for (int k = 0; k < 64; k++) {
            float ae = Ls[k * 132 + tid] * invnv;
            float h = bf_hi(ae);
            ah[(size_t)k * P_] = __float2bfloat16_rn(ae);
            al[(size_t)k * P_] = __float2bfloat16_rn(ae - h);
        }
    }
    if (tid < 64) {
        float s = 0.f;
        for (int p = 0; p < 128; p++) s += Ls[tid * 132 + p];
        atomicAdd(&g_asum[n * K_ + tid], s);
    }
}

// ---------------- k3: vlad GEMM, double-buffered pipeline --------------------
// block = (n, 128-d chunk), 512 threads (16 warps).
// vladT[128 d, 64 k] = X[d, p] * Aeff[k, p]^T   over p = 0..4095
#define ST3 136
#define XPART (128 * ST3)
#define APART (64 * ST3)
#define BUF_B ((2 * XPART + 2 * APART) * 2)   // 104448 bytes
#define K3_SMEM (2 * BUF_B)                    // 208896 bytes
#define NCH (P_ / 128)

__global__ __launch_bounds__(512) void k3_mma(const float* __restrict__ x) {
    extern __shared__ char sm3[];

    const int n  = blockIdx.y;
    const int d0 = blockIdx.x * 128;
    const int tid = threadIdx.x;
    const int w = tid >> 5, lane = tid & 31;
    const int g = lane >> 2, tc = lane & 3;
    const int mt = w >> 1;
    const int nh = (w & 1) * 32;

    const float* xn = x + (size_t)n * D_ * P_ + (size_t)d0 * P_;
    const __nv_bfloat16* gah = g_ah + (size_t)n * K_ * P_;
    const __nv_bfloat16* gal = g_al + (size_t)n * K_ * P_;

    float acc[4][4];
    #pragma unroll
    for (int t = 0; t < 4; t++)
        #pragma unroll
        for (int q = 0; q < 4; q++) acc[t][q] = 0.f;

    const int c4 = tid & 31;      // p-group (4 pixels)
    const int r0 = tid >> 5;      // 0..15
    const int arow = tid >> 4;    // 0..31 (A cp.async row per 512-thread pass? no:)
    // A cp.async mapping: idx = tid + j*512, row = idx>>4 (0..63), seg = idx&15

    float4 xv[8];

    // ---- prologue: stage chunk 0 into buffer 0 ----
    {
        char* buf = sm3;
        __nv_bfloat16* Xh = (__nv_bfloat16*)buf;
        __nv_bfloat16* Xl = Xh + XPART;
        __nv_bfloat16* Ahs = Xl + XPART;
        __nv_bfloat16* Als = Ahs + APART;
        #pragma unroll
        for (int j = 0; j < 2; j++) {
            int idx = tid + j * 512;
            int row = idx >> 4, seg = idx & 15;
            cp16(Ahs + row * ST3 + seg * 8, gah + (size_t)row * P_ + seg * 8);
            cp16(Als + row * ST3 + seg * 8, gal + (size_t)row * P_ + seg * 8);
        }
        CP_COMMIT();
        #pragma unroll
        for (int rr = 0; rr < 8; rr++)
            xv[rr] = *(const float4*)(xn + (size_t)(r0 + rr * 16) * P_ + c4 * 4);
        #pragma unroll
        for (int rr = 0; rr < 8; rr++) {
            int row = r0 + rr * 16;
            uint2 h, l; split4(xv[rr], h, l);
            *(uint2*)(Xh + row * ST3 + c4 * 4) = h;
            *(uint2*)(Xl + row * ST3 + c4 * 4) = l;
        }
        CP_WAIT0();
        __syncthreads();
    }

    for (int pc = 0; pc < NCH; pc++) {
        const int b = pc & 1;
        char* buf = sm3 + b * BUF_B;
        const __nv_bfloat16* Xh = (const __nv_bfloat16*)buf;
        const __nv_bfloat16* Xl = Xh + XPART;
        const __nv_bfloat16* Ahs = Xl + XPART;
        const __nv_bfloat16* Als = Ahs + APART;

        char* nbuf = sm3 + (b ^ 1) * BUF_B;
        __nv_bfloat16* nXh = (__nv_bfloat16*)nbuf;
        __nv_bfloat16* nXl = nXh + XPART;
        __nv_bfloat16* nAh = nXl + XPART;
        __nv_bfloat16* nAl = nAh + APART;

        const bool more = (pc + 1 < NCH);
        if (more) {
            const int pb = (pc + 1) * 128;
            #pragma unroll
            for (int j = 0; j < 2; j++) {
                int idx = tid + j * 512;
                int row = idx >> 4, seg = idx & 15;
                cp16(nAh + row * ST3 + seg * 8, gah + (size_t)row * P_ + pb + seg * 8);
                cp16(nAl + row * ST3 + seg * 8, gal + (size_t)row * P_ + pb + seg * 8);
            }
            CP_COMMIT();
            #pragma unroll
            for (int rr = 0; rr < 8; rr++)
                xv[rr] = *(const float4*)(xn + (size_t)(r0 + rr * 16) * P_ + pb + c4 * 4);
        }

        // ---- MMA on current buffer ----
        #pragma unroll
        for (int ks = 0; ks < 8; ks++) {
            const int kb = ks * 16;
            uint32_t Bh[4][2], Bl[4][2];
            #pragma unroll
            for (int t = 0; t < 4; t++) {
                int col = nh + t * 8 + g;
                Bh[t][0] = *(const uint32_t*)(Ahs + col * ST3 + kb + tc * 2);
                Bh[t][1] = *(const uint32_t*)(Ahs + col * ST3 + kb + 8 + tc * 2);
                Bl[t][0] = *(const uint32_t*)(Als + col * ST3 + kb + tc * 2);
                Bl[t][1] = *(const uint32_t*)(Als + col * ST3 + kb + 8 + tc * 2);
            }
            const int ar = mt * 16 + g;
            uint32_t Ah[4], Al[4];
            Ah[0] = *(const uint32_t*)(Xh + ar * ST3 + kb + tc * 2);
            Ah[1] = *(const uint32_t*)(Xh + (ar + 8) * ST3 + kb + tc * 2);
            Ah[2] = *(const uint32_t*)(Xh + ar * ST3 + kb + 8 + tc * 2);
            Ah[3] = *(const uint32_t*)(Xh + (ar + 8) * ST3 + kb + 8 + tc * 2);
            Al[0] = *(const uint32_t*)(Xl + ar * ST3 + kb + tc * 2);
            Al[1] = *(const uint32_t*)(Xl + (ar + 8) * ST3 + kb + tc * 2);
            Al[2] = *(const uint32_t*)(Xl + ar * ST3 + kb + 8 + tc * 2);
            Al[3] = *(const uint32_t*)(Xl + (ar + 8) * ST3 + kb + 8 + tc * 2);
            #pragma unroll
            for (int t = 0; t < 4; t++) {
                mma_bf16(acc[t], Ah, Bh[t]);
                mma_bf16(acc[t], Ah, Bl[t]);
                mma_bf16(acc[t], Al, Bh[t]);
            }
        }

        if (more) {
            #pragma unroll
            for (int rr = 0; rr < 8; rr++) {
                int row = r0 + rr * 16;
                uint2 h, l; split4(xv[rr], h, l);
                *(uint2*)(nXh + row * ST3 + c4 * 4) = h;
                *(uint2*)(nXl + row * ST3 + c4 * 4) = l;
            }
            CP_WAIT0();
        }
        __syncthreads();
    }

    // epilogue: acc (row=d_local, col=k) -> g_vlad[n][k][d]
    float* vb = g_vlad + (size_t)n * K_ * D_ + d0;
    const int r = mt * 16 + g;
    #pragma unroll
    for (int t = 0; t < 4; t++) {
        int kc = nh + t * 8 + tc * 2;
        vb[(size_t)kc * D_ + r]           = acc[t][0];
        vb[(size_t)(kc + 1) * D_ + r]     = acc[t][1];
        vb[(size_t)kc * D_ + r + 8]       = acc[t][2];
        vb[(size_t)(kc + 1) * D_ + r + 8] = acc[t][3];
    }
}

// ---------------- k4a: centroid subtraction + intra-normalize -----------------
__global__ __launch_bounds__(128) void k4a_finalize(
        const float* __restrict__ cent, float* __restrict__ out) {
    const int k = blockIdx.x, n = blockIdx.y;
    const int tid = threadIdx.x;
    const float asum = g_asum[n * K_ + k];
    const float* vl = g_vlad + ((size_t)n * K_ + k) * D_;
    const float* ck = cent + (size_t)k * D_;

    float t[4];
    float s2 = 0.f;
    #pragma unroll
    for (int r = 0; r < 4; r++) {
        int d = r * 128 + tid;
        t[r] = vl[d] - asum * ck[d];
        s2 += t[r] * t[r];
    }
    #pragma unroll
    for (int o = 16; o > 0; o >>= 1) s2 += __shfl_xor_sync(0xffffffffu, s2, o);
    __shared__ float red[4];
    if ((tid & 31) == 0) red[tid >> 5] = s2;
    __syncthreads();
    float total = red[0] + red[1] + red[2] + red[3];
    float inv = 1.0f / fmaxf(sqrtf(total), EPSF);

    float* o = out + ((size_t)n * K_ + k) * D_;
    #pragma unroll
    for (int r = 0; r < 4; r++) o[r * 128 + tid] = t[r] * inv;
    if (tid == 0) atomicAdd(&g_gnorm2[n], total * inv * inv);
}

// ---------------- k4b: global L2 scale -----------------------------------------
__global__ void k4b_global(float* __restrict__ out) {
    int i = blockIdx.x * 256 + threadIdx.x;
    int n = i >> 15;
    float inv = 1.0f / fmaxf(sqrtf(g_gnorm2[n]), EPSF);
    out[i] *= inv;
}

// ---------------- launch --------------------------------------------------------
extern "C" void kernel_launch(void* const* d_in, const int* in_sizes, int n_in,
                              void* d_out, int out_size) {
    const float* x = (const float*)d_in[0];
    const float* w = (const float*)d_in[1];
    const float* c = (const float*)d_in[2];
    float* out = (float*)d_out;

    static bool attr_done = false;
    if (!attr_done) {
        cudaFuncSetAttribute(k2_mma, cudaFuncAttributeMaxDynamicSharedMemorySize, K2_SMEM);
        cudaFuncSetAttribute(k3_mma, cudaFuncAttributeMaxDynamicSharedMemorySize, K3_SMEM);
        attr_done = true;
    }

    k0_zero<<<8, 256>>>();

    dim3 g2(P_ / 128, N_);
    k2_mma<<<g2, 128, K2_SMEM>>>(x, w);

    dim3 g3(D_ / 128, N_);
    k3_mma<<<g3, 512, K3_SMEM>>>(x);

    dim3 g4(K_, N_);
    k4a_finalize<<<g4, 128>>>(c, out);

    k4b_global<<<(N_ * K_ * D_) / 256, 256>>>(out);
}

// round 5
// speedup vs baseline: 2.5336x; 1.0595x over previous
#include <cuda_runtime.h>
#include <cuda_bf16.h>
#include <math.h>
#include <stdint.h>

#define N_  32
#define D_  512
#define P_  4096
#define K_  64
#define EPSF 1e-12f

// ---------------- scratch (device globals) ----------------------------------
__device__ __nv_bfloat16 g_ah[(size_t)N_ * K_ * P_];    // a*invn hi (16 MB)
__device__ __nv_bfloat16 g_al[(size_t)N_ * K_ * P_];    // a*invn lo (16 MB)
__device__ __nv_bfloat16 g_wh[K_ * D_];                 // W hi (64 KB)
__device__ __nv_bfloat16 g_wl[K_ * D_];                 // W lo (64 KB)
__device__ float g_asum[N_ * K_];
__device__ float g_vlad[(size_t)N_ * K_ * D_];          // 4 MB
__device__ float g_gnorm2[N_];

// ---------------- helpers ----------------------------------------------------
__device__ __forceinline__ uint32_t smem_u32(const void* p) {
    uint32_t a;
    asm("{ .reg .u64 t; cvta.to.shared.u64 t, %1; cvt.u32.u64 %0, t; }" : "=r"(a) : "l"(p));
    return a;
}
__device__ __forceinline__ void mma_bf16(float* c, const uint32_t* a, const uint32_t* b) {
    asm volatile(
        "mma.sync.aligned.m16n8k16.row.col.f32.bf16.bf16.f32 "
        "{%0,%1,%2,%3}, {%4,%5,%6,%7}, {%8,%9}, {%0,%1,%2,%3};"
        : "+f"(c[0]), "+f"(c[1]), "+f"(c[2]), "+f"(c[3])
        : "r"(a[0]), "r"(a[1]), "r"(a[2]), "r"(a[3]), "r"(b[0]), "r"(b[1]));
}
__device__ __forceinline__ uint32_t pack2(float a, float b) {
    __nv_bfloat162 h = __floats2bfloat162_rn(a, b);
    return *(uint32_t*)&h;
}
__device__ __forceinline__ float bf_hi(float v) {
    return __bfloat162float(__float2bfloat16_rn(v));
}
__device__ __forceinline__ void split4(float4 v, uint2& h, uint2& l) {
    float hx = bf_hi(v.x), hy = bf_hi(v.y), hz = bf_hi(v.z), hw = bf_hi(v.w);
    h.x = pack2(v.x, v.y);           h.y = pack2(v.z, v.w);
    l.x = pack2(v.x - hx, v.y - hy); l.y = pack2(v.z - hz, v.w - hw);
}
__device__ __forceinline__ void cp16(void* dst_smem, const void* src) {
    asm volatile("cp.async.cg.shared.global [%0], [%1], 16;"
                 :: "r"(smem_u32(dst_smem)), "l"(src) : "memory");
}
#define CP_COMMIT() asm volatile("cp.async.commit_group;" ::: "memory")
#define CP_WAIT0()  asm volatile("cp.async.wait_group 0;" ::: "memory")

// ---------------- k0: zero scratch + split W into bf16 hi/lo ------------------
__global__ void k0_init(const float* __restrict__ wgt) {
    int i = blockIdx.x * 256 + threadIdx.x;
    if (i < N_ * K_) g_asum[i] = 0.f;
    if (i < N_)      g_gnorm2[i] = 0.f;
    // W split: 32768 elems, grid covers with stride
    for (int e = i; e < K_ * D_; e += gridDim.x * 256) {
        float v = wgt[e];
        float h = bf_hi(v);
        g_wh[e] = __float2bfloat16_rn(v);
        g_wl[e] = __float2bfloat16_rn(v - h);
    }
}

// ---------------- k2: fused norm + logits GEMM + softmax + a_eff + asum ------
// block = (n, 128 pixels), 128 threads (4 warps). Double-buffered pipeline.
#define ST2 40
#define WPART (64 * ST2)
#define TPART (128 * ST2)
#define BUF2_B ((WPART * 2 + TPART * 2) * 2)        // 30720 bytes per buffer
#define K2_SMEM (2 * BUF2_B + 512)                  // staging (Ls unioned) + sInv

__global__ __launch_bounds__(128) void k2_mma(const float* __restrict__ x) {
    extern __shared__ char sm2[];
    float* Ls = (float*)sm2;                        // [64][132] — UNION with staging
    float* sInv = (float*)(sm2 + 2 * BUF2_B);       // [128]

    const int n  = blockIdx.y;
    const int p0 = blockIdx.x * 128;
    const int tid = threadIdx.x;
    const int w = tid >> 5, lane = tid & 31;
    const int g = lane >> 2, tc = lane & 3;

    float acc[4][4][4];
    #pragma unroll
    for (int i = 0; i < 4; i++)
        #pragma unroll
        for (int j = 0; j < 4; j++)
            #pragma unroll
            for (int q = 0; q < 4; q++) acc[i][j][q] = 0.f;

    const float* xb = x + (size_t)n * D_ * P_ + p0 + tid;
    float ss = 0.f;

    const int wrow = tid >> 1;          // W cp.async row (0..63)
    const int wseg = (tid & 1) * 16;    // elem offset (two 16B segs per thread)

    float xr[32];

    // ---- prologue: stage chunk 0 into buffer 0 ----
    {
        char* buf = sm2;
        __nv_bfloat16* Wh = (__nv_bfloat16*)buf;
        __nv_bfloat16* Wl = Wh + WPART;
        __nv_bfloat16* Th = Wl + WPART;
        __nv_bfloat16* Tl = Th + TPART;
        cp16(Wh + wrow * ST2 + wseg,     g_wh + wrow * D_ + wseg);
        cp16(Wh + wrow * ST2 + wseg + 8, g_wh + wrow * D_ + wseg + 8);
        cp16(Wl + wrow * ST2 + wseg,     g_wl + wrow * D_ + wseg);
        cp16(Wl + wrow * ST2 + wseg + 8, g_wl + wrow * D_ + wseg + 8);
        CP_COMMIT();
        #pragma unroll
        for (int dd = 0; dd < 32; dd++) xr[dd] = xb[(size_t)dd * P_];
        #pragma unroll
        for (int dd = 0; dd < 32; dd += 4) {
            float4 v = {xr[dd], xr[dd + 1], xr[dd + 2], xr[dd + 3]};
            ss += v.x * v.x + v.y * v.y + v.z * v.z + v.w * v.w;
            uint2 h, l; split4(v, h, l);
            *(uint2*)(Th + tid * ST2 + dd) = h;
            *(uint2*)(Tl + tid * ST2 + dd) = l;
        }
        CP_WAIT0();
        __syncthreads();
    }

    for (int dc = 0; dc < 16; dc++) {
        const int b = dc & 1;
        char* buf = sm2 + b * BUF2_B;
        const __nv_bfloat16* Wh = (const __nv_bfloat16*)buf;
        const __nv_bfloat16* Wl = Wh + WPART;
        const __nv_bfloat16* Th = Wl + WPART;
        const __nv_bfloat16* Tl = Th + TPART;

        char* nbuf = sm2 + (b ^ 1) * BUF2_B;
        __nv_bfloat16* nWh = (__nv_bfloat16*)nbuf;
        __nv_bfloat16* nWl = nWh + WPART;
        __nv_bfloat16* nTh = nWl + WPART;
        __nv_bfloat16* nTl = nTh + TPART;

        const bool more = (dc + 1 < 16);
        if (more) {
            const int nd0 = (dc + 1) * 32;
            cp16(nWh + wrow * ST2 + wseg,     g_wh + wrow * D_ + nd0 + wseg);
            cp16(nWh + wrow * ST2 + wseg + 8, g_wh + wrow * D_ + nd0 + wseg + 8);
            cp16(nWl + wrow * ST2 + wseg,     g_wl + wrow * D_ + nd0 + wseg);
            cp16(nWl + wrow * ST2 + wseg + 8, g_wl + wrow * D_ + nd0 + wseg + 8);
            CP_COMMIT();
            #pragma unroll
            for (int dd = 0; dd < 32; dd++) xr[dd] = xb[(size_t)(nd0 + dd) * P_];
        }

        // ---- MMA on current buffer ----
        #pragma unroll
        for (int ks = 0; ks < 2; ks++) {
            const int kb = ks * 16;
            uint32_t Bh[4][2], Bl[4][2];
            #pragma unroll
            for (int t = 0; t < 4; t++) {
                int col = w * 32 + t * 8 + g;
                Bh[t][0] = *(const uint32_t*)(Th + col * ST2 + kb + tc * 2);
                Bh[t][1] = *(const uint32_t*)(Th + col * ST2 + kb + 8 + tc * 2);
                Bl[t][0] = *(const uint32_t*)(Tl + col * ST2 + kb + tc * 2);
                Bl[t][1] = *(const uint32_t*)(Tl + col * ST2 + kb + 8 + tc * 2);
            }
            #pragma unroll
            for (int mt = 0; mt < 4; mt++) {
                const int ar = mt * 16 + g;
                uint32_t Ah[4], Al[4];
                Ah[0] = *(const uint32_t*)(Wh + ar * ST2 + kb + tc * 2);
                Ah[1] = *(const uint32_t*)(Wh + (ar + 8) * ST2 + kb + tc * 2);
                Ah[2] = *(const uint32_t*)(Wh + ar * ST2 + kb + 8 + tc * 2);
                Ah[3] = *(const uint32_t*)(Wh + (ar + 8) * ST2 + kb + 8 + tc * 2);
                Al[0] = *(const uint32_t*)(Wl + ar * ST2 + kb + tc * 2);
                Al[1] = *(const uint32_t*)(Wl + (ar + 8) * ST2 + kb + tc * 2);
                Al[2] = *(const uint32_t*)(Wl + ar * ST2 + kb + 8 + tc * 2);
                Al[3] = *(const uint32_t*)(Wl + (ar + 8) * ST2 + kb + 8 + tc * 2);
                #pragma unroll
                for (int t = 0; t < 4; t++) {
                    mma_bf16(acc[mt][t], Ah, Bh[t]);
                    mma_bf16(acc[mt][t], Ah, Bl[t]);
                    mma_bf16(acc[mt][t], Al, Bh[t]);
                }
            }
        }

        if (more) {
            #pragma unroll
            for (int dd = 0; dd < 32; dd += 4) {
                float4 v = {xr[dd], xr[dd + 1], xr[dd + 2], xr[dd + 3]};
                ss += v.x * v.x + v.y * v.y + v.z * v.z + v.w * v.w;
                uint2 h, l; split4(v, h, l);
                *(uint2*)(nTh + tid * ST2 + dd) = h;
                *(uint2*)(nTl + tid * ST2 + dd) = l;
            }
            CP_WAIT0();
        }
        __syncthreads();
    }

    const float invnv = 1.0f / fmaxf(sqrtf(ss), EPSF);
    sInv[tid] = invnv;
    __syncthreads();

    // epilogue: scale by invn, stage logits into Ls (staging buffers dead now)
    #pragma unroll
    for (int mt = 0; mt < 4; mt++)
        #pragma unroll
        for (int t = 0; t < 4; t++) {
            int col = w * 32 + t * 8 + tc * 2;
            int row = mt * 16 + g;
            Ls[row * 132 + col]           = acc[mt][t][0] * sInv[col];
            Ls[row * 132 + col + 1]       = acc[mt][t][1] * sInv[col + 1];
            Ls[(row + 8) * 132 + col]     = acc[mt][t][2] * sInv[col];
            Ls[(row + 8) * 132 + col + 1] = acc[mt][t][3] * sInv[col + 1];
        }
    __syncthreads();

    // softmax over clusters; one thread per pixel column
    {
        float m = -1e30f;
        for (int k = 0; k < 64; k++) m = fmaxf(m, Ls[k * 132 + tid]);
        float s = 0.f;
        for (int k = 0; k < 64; k++) {
            float e = expf(Ls[k * 132 + tid] - m);
            Ls[k * 132 + tid] = e;
            s += e;
        }
        float inv = 1.0f / s;
        for (int k = 0; k < 64; k++) Ls[k * 132 + tid] *= inv;
    }
    __syncthreads();

    // write a_eff = a * invn, split bf16 hi/lo
    {
        __nv_bfloat16* ah = g_ah + (size_t)n * K_ * P_ + p0 + tid;
        __nv_bfloat16* al = g_al + (size_t)n * K_ * P_ + p0 + tid;
        for (int k = 0; k < 64; k++) {
            float ae = Ls[k * 132 + tid] * invnv;
            float h = bf_hi(ae);
            ah[(size_t)k * P_] = __float2bfloat16_rn(ae);
            al[(size_t)k * P_] = __float2bfloat16_rn(ae - h);
        }
    }
    if (tid < 64) {
        float s = 0.f;
        for (int p = 0; p < 128; p++) s += Ls[tid * 132 + p];
        atomicAdd(&g_asum[n * K_ + tid], s);
    }
}

// ---------------- k3: vlad GEMM, double-buffered pipeline --------------------
#define ST3 136
#define XPART (128 * ST3)
#define APART (64 * ST3)
#define BUF_B ((2 * XPART + 2 * APART) * 2)   // 104448 bytes
#define K3_SMEM (2 * BUF_B)                    // 208896 bytes
#define NCH (P_ / 128)

__global__ __launch_bounds__(512) void k3_mma(const float* __restrict__ x) {
    extern __shared__ char sm3[];

    const int n  = blockIdx.y;
    const int d0 = blockIdx.x * 128;
    const int tid = threadIdx.x;
    const int w = tid >> 5, lane = tid & 31;
    const int g = lane >> 2, tc = lane & 3;
    const int mt = w >> 1;
    const int nh = (w & 1) * 32;

    const float* xn = x + (size_t)n * D_ * P_ + (size_t)d0 * P_;
    const __nv_bfloat16* gah = g_ah + (size_t)n * K_ * P_;
    const __nv_bfloat16* gal = g_al + (size_t)n * K_ * P_;

    float acc[4][4];
    #pragma unroll
    for (int t = 0; t < 4; t++)
        #pragma unroll
        for (int q = 0; q < 4; q++) acc[t][q] = 0.f;

    const int c4 = tid & 31;
    const int r0 = tid >> 5;

    float4 xv[8];

    // ---- prologue: stage chunk 0 into buffer 0 ----
    {
        char* buf = sm3;
        __nv_bfloat16* Xh = (__nv_bfloat16*)buf;
        __nv_bfloat16* Xl = Xh + XPART;
        __nv_bfloat16* Ahs = Xl + XPART;
        __nv_bfloat16* Als = Ahs + APART;
        #pragma unroll
        for (int j = 0; j < 2; j++) {
            int idx = tid + j * 512;
            int row = idx >> 4, seg = idx & 15;
            cp16(Ahs + row * ST3 + seg * 8, gah + (size_t)row * P_ + seg * 8);
            cp16(Als + row * ST3 + seg * 8, gal + (size_t)row * P_ + seg * 8);
        }
        CP_COMMIT();
        #pragma unroll
        for (int rr = 0; rr < 8; rr++)
            xv[rr] = *(const float4*)(xn + (size_t)(r0 + rr * 16) * P_ + c4 * 4);
        #pragma unroll
        for (int rr = 0; rr < 8; rr++) {
            int row = r0 + rr * 16;
            uint2 h, l; split4(xv[rr], h, l);
            *(uint2*)(Xh + row * ST3 + c4 * 4) = h;
            *(uint2*)(Xl + row * ST3 + c4 * 4) = l;
        }
        CP_WAIT0();
        __syncthreads();
    }

    for (int pc = 0; pc < NCH; pc++) {
        const int b = pc & 1;
        char* buf = sm3 + b * BUF_B;
        const __nv_bfloat16* Xh = (const __nv_bfloat16*)buf;
        const __nv_bfloat16* Xl = Xh + XPART;
        const __nv_bfloat16* Ahs = Xl + XPART;
        const __nv_bfloat16* Als = Ahs + APART;

        char* nbuf = sm3 + (b ^ 1) * BUF_B;
        __nv_bfloat16* nXh = (__nv_bfloat16*)nbuf;
        __nv_bfloat16* nXl = nXh + XPART;
        __nv_bfloat16* nAh = nXl + XPART;
        __nv_bfloat16* nAl = nAh + APART;

        const bool more = (pc + 1 < NCH);
        if (more) {
            const int pb = (pc + 1) * 128;
            #pragma unroll
            for (int j = 0; j < 2; j++) {
                int idx = tid + j * 512;
                int row = idx >> 4, seg = idx & 15;
                cp16(nAh + row * ST3 + seg * 8, gah + (size_t)row * P_ + pb + seg * 8);
                cp16(nAl + row * ST3 + seg * 8, gal + (size_t)row * P_ + pb + seg * 8);
            }
            CP_COMMIT();
            #pragma unroll
            for (int rr = 0; rr < 8; rr++)
                xv[rr] = *(const float4*)(xn + (size_t)(r0 + rr * 16) * P_ + pb + c4 * 4);
        }

        #pragma unroll
        for (int ks = 0; ks < 8; ks++) {
            const int kb = ks * 16;
            uint32_t Bh[4][2], Bl[4][2];
            #pragma unroll
            for (int t = 0; t < 4; t++) {
                int col = nh + t * 8 + g;
                Bh[t][0] = *(const uint32_t*)(Ahs + col * ST3 + kb + tc * 2);
                Bh[t][1] = *(const uint32_t*)(Ahs + col * ST3 + kb + 8 + tc * 2);
                Bl[t][0] = *(const uint32_t*)(Als + col * ST3 + kb + tc * 2);
                Bl[t][1] = *(const uint32_t*)(Als + col * ST3 + kb + 8 + tc * 2);
            }
            const int ar = mt * 16 + g;
            uint32_t Ah[4], Al[4];
            Ah[0] = *(const uint32_t*)(Xh + ar * ST3 + kb + tc * 2);
            Ah[1] = *(const uint32_t*)(Xh + (ar + 8) * ST3 + kb + tc * 2);
            Ah[2] = *(const uint32_t*)(Xh + ar * ST3 + kb + 8 + tc * 2);
            Ah[3] = *(const uint32_t*)(Xh + (ar + 8) * ST3 + kb + 8 + tc * 2);
            Al[0] = *(const uint32_t*)(Xl + ar * ST3 + kb + tc * 2);
            Al[1] = *(const uint32_t*)(Xl + (ar + 8) * ST3 + kb + tc * 2);
            Al[2] = *(const uint32_t*)(Xl + ar * ST3 + kb + 8 + tc * 2);
            Al[3] = *(const uint32_t*)(Xl + (ar + 8) * ST3 + kb + 8 + tc * 2);
            #pragma unroll
            for (int t = 0; t < 4; t++) {
                mma_bf16(acc[t], Ah, Bh[t]);
                mma_bf16(acc[t], Ah, Bl[t]);
                mma_bf16(acc[t], Al, Bh[t]);
            }
        }

        if (more) {
            #pragma unroll
            for (int rr = 0; rr < 8; rr++) {
                int row = r0 + rr * 16;
                uint2 h, l; split4(xv[rr], h, l);
                *(uint2*)(nXh + row * ST3 + c4 * 4) = h;
                *(uint2*)(nXl + row * ST3 + c4 * 4) = l;
            }
            CP_WAIT0();
        }
        __syncthreads();
    }

    float* vb = g_vlad + (size_t)n * K_ * D_ + d0;
    const int r = mt * 16 + g;
    #pragma unroll
    for (int t = 0; t < 4; t++) {
        int kc = nh + t * 8 + tc * 2;
        vb[(size_t)kc * D_ + r]           = acc[t][0];
        vb[(size_t)(kc + 1) * D_ + r]     = acc[t][1];
        vb[(size_t)kc * D_ + r + 8]       = acc[t][2];
        vb[(size_t)(kc + 1) * D_ + r + 8] = acc[t][3];
    }
}

// ---------------- k4a: centroid subtraction + intra-normalize -----------------
__global__ __launch_bounds__(128) void k4a_finalize(
        const float* __restrict__ cent, float* __restrict__ out) {
    const int k = blockIdx.x, n = blockIdx.y;
    const int tid = threadIdx.x;
    const float asum = g_asum[n * K_ + k];
    const float* vl = g_vlad + ((size_t)n * K_ + k) * D_;
    const float* ck = cent + (size_t)k * D_;

    float t[4];
    float s2 = 0.f;
    #pragma unroll
    for (int r = 0; r < 4; r++) {
        int d = r * 128 + tid;
        t[r] = vl[d] - asum * ck[d];
        s2 += t[r] * t[r];
    }
    #pragma unroll
    for (int o = 16; o > 0; o >>= 1) s2 += __shfl_xor_sync(0xffffffffu, s2, o);
    __shared__ float red[4];
    if ((tid & 31) == 0) red[tid >> 5] = s2;
    __syncthreads();
    float total = red[0] + red[1] + red[2] + red[3];
    float inv = 1.0f / fmaxf(sqrtf(total), EPSF);

    float* o = out + ((size_t)n * K_ + k) * D_;
    #pragma unroll
    for (int r = 0; r < 4; r++) o[r * 128 + tid] = t[r] * inv;
    if (tid == 0) atomicAdd(&g_gnorm2[n], total * inv * inv);
}

// ---------------- k4b: global L2 scale -----------------------------------------
__global__ void k4b_global(float* __restrict__ out) {
    int i = blockIdx.x * 256 + threadIdx.x;
    int n = i >> 15;
    float inv = 1.0f / fmaxf(sqrtf(g_gnorm2[n]), EPSF);
    out[i] *= inv;
}

// ---------------- launch --------------------------------------------------------
extern "C" void kernel_launch(void* const* d_in, const int* in_sizes, int n_in,
                              void* d_out, int out_size) {
    const float* x = (const float*)d_in[0];
    const float* w = (const float*)d_in[1];
    const float* c = (const float*)d_in[2];
    float* out = (float*)d_out;

    static bool attr_done = false;
    if (!attr_done) {
        cudaFuncSetAttribute(k2_mma, cudaFuncAttributeMaxDynamicSharedMemorySize, K2_SMEM);
        cudaFuncSetAttribute(k3_mma, cudaFuncAttributeMaxDynamicSharedMemorySize, K3_SMEM);
        attr_done = true;
    }

    k0_init<<<32, 256>>>(w);

    dim3 g2(P_ / 128, N_);
    k2_mma<<<g2, 128, K2_SMEM>>>(x);

    dim3 g3(D_ / 128, N_);
    k3_mma<<<g3, 512, K3_SMEM>>>(x);

    dim3 g4(K_, N_);
    k4a_finalize<<<g4, 128>>>(c, out);

    k4b_global<<<(N_ * K_ * D_) / 256, 256>>>(out);
}

// round 6
// speedup vs baseline: 2.9452x; 1.1625x over previous
#include <cuda_runtime.h>
#include <cuda_bf16.h>
#include <math.h>
#include <stdint.h>

#define N_  32
#define D_  512
#define P_  4096
#define K_  64
#define EPSF 1e-12f

// ---------------- scratch (device globals) ----------------------------------
__device__ __nv_bfloat16 g_ah[(size_t)N_ * K_ * P_];    // a*invn hi (16 MB)
__device__ __nv_bfloat16 g_al[(size_t)N_ * K_ * P_];    // a*invn lo (16 MB)
__device__ __nv_bfloat16 g_wh[K_ * D_];                 // W bf16 (64 KB)
__device__ float g_asum[N_ * K_];
__device__ float g_vlad[(size_t)N_ * K_ * D_];          // 4 MB
__device__ float g_gnorm2[N_];

// ---------------- helpers ----------------------------------------------------
__device__ __forceinline__ uint32_t smem_u32(const void* p) {
    uint32_t a;
    asm("{ .reg .u64 t; cvta.to.shared.u64 t, %1; cvt.u32.u64 %0, t; }" : "=r"(a) : "l"(p));
    return a;
}
__device__ __forceinline__ void mma_bf16(float* c, const uint32_t* a, const uint32_t* b) {
    asm volatile(
        "mma.sync.aligned.m16n8k16.row.col.f32.bf16.bf16.f32 "
        "{%0,%1,%2,%3}, {%4,%5,%6,%7}, {%8,%9}, {%0,%1,%2,%3};"
        : "+f"(c[0]), "+f"(c[1]), "+f"(c[2]), "+f"(c[3])
        : "r"(a[0]), "r"(a[1]), "r"(a[2]), "r"(a[3]), "r"(b[0]), "r"(b[1]));
}
__device__ __forceinline__ uint32_t pack2(float a, float b) {
    __nv_bfloat162 h = __floats2bfloat162_rn(a, b);
    return *(uint32_t*)&h;
}
__device__ __forceinline__ float bf_hi(float v) {
    return __bfloat162float(__float2bfloat16_rn(v));
}
__device__ __forceinline__ void split4(float4 v, uint2& h, uint2& l) {
    float hx = bf_hi(v.x), hy = bf_hi(v.y), hz = bf_hi(v.z), hw = bf_hi(v.w);
    h.x = pack2(v.x, v.y);           h.y = pack2(v.z, v.w);
    l.x = pack2(v.x - hx, v.y - hy); l.y = pack2(v.z - hz, v.w - hw);
}
__device__ __forceinline__ void pack4h(float4 v, uint2& h) {
    h.x = pack2(v.x, v.y);  h.y = pack2(v.z, v.w);
}
__device__ __forceinline__ void cp16(void* dst_smem, const void* src) {
    asm volatile("cp.async.cg.shared.global [%0], [%1], 16;"
                 :: "r"(smem_u32(dst_smem)), "l"(src) : "memory");
}
#define CP_COMMIT() asm volatile("cp.async.commit_group;" ::: "memory")
#define CP_WAIT0()  asm volatile("cp.async.wait_group 0;" ::: "memory")

// ---------------- k0: zero scratch + convert W to bf16 ------------------------
__global__ void k0_init(const float* __restrict__ wgt) {
    int i = blockIdx.x * 256 + threadIdx.x;
    if (i < N_ * K_) g_asum[i] = 0.f;
    if (i < N_)      g_gnorm2[i] = 0.f;
    for (int e = i; e < K_ * D_; e += gridDim.x * 256)
        g_wh[e] = __float2bfloat16_rn(wgt[e]);
}

// ---------------- k2: fused norm + logits GEMM + softmax + a_eff + asum ------
// block = (n, 128 pixels), 128 threads (4 warps). Double-buffered, single bf16 pass.
#define ST2 40
#define WPART (64 * ST2)
#define TPART (128 * ST2)
#define BUF2_B ((WPART + TPART) * 2)            // 15360 bytes per buffer
#define LS_B (64 * 132 * 4)                     // 33792
#define K2_SMEM (LS_B + 512)                    // Ls unioned over both buffers

__global__ __launch_bounds__(128) void k2_mma(const float* __restrict__ x) {
    extern __shared__ char sm2[];
    float* Ls = (float*)sm2;                    // [64][132] — UNION with staging
    float* sInv = (float*)(sm2 + LS_B);         // [128]

    const int n  = blockIdx.y;
    const int p0 = blockIdx.x * 128;
    const int tid = threadIdx.x;
    const int w = tid >> 5, lane = tid & 31;
    const int g = lane >> 2, tc = lane & 3;

    float acc[4][4][4];
    #pragma unroll
    for (int i = 0; i < 4; i++)
        #pragma unroll
        for (int j = 0; j < 4; j++)
            #pragma unroll
            for (int q = 0; q < 4; q++) acc[i][j][q] = 0.f;

    const float* xb = x + (size_t)n * D_ * P_ + p0 + tid;
    float ss = 0.f;

    const int wrow = tid >> 1;          // W cp.async row (0..63)
    const int wseg = (tid & 1) * 16;

    float xr[32];

    // ---- prologue: stage chunk 0 into buffer 0 ----
    {
        char* buf = sm2;
        __nv_bfloat16* Wh = (__nv_bfloat16*)buf;
        __nv_bfloat16* Th = Wh + WPART;
        cp16(Wh + wrow * ST2 + wseg,     g_wh + wrow * D_ + wseg);
        cp16(Wh + wrow * ST2 + wseg + 8, g_wh + wrow * D_ + wseg + 8);
        CP_COMMIT();
        #pragma unroll
        for (int dd = 0; dd < 32; dd++) xr[dd] = xb[(size_t)dd * P_];
        #pragma unroll
        for (int dd = 0; dd < 32; dd += 4) {
            float4 v = {xr[dd], xr[dd + 1], xr[dd + 2], xr[dd + 3]};
            ss += v.x * v.x + v.y * v.y + v.z * v.z + v.w * v.w;
            uint2 h; pack4h(v, h);
            *(uint2*)(Th + tid * ST2 + dd) = h;
        }
        CP_WAIT0();
        __syncthreads();
    }

    for (int dc = 0; dc < 16; dc++) {
        const int b = dc & 1;
        char* buf = sm2 + b * BUF2_B;
        const __nv_bfloat16* Wh = (const __nv_bfloat16*)buf;
        const __nv_bfloat16* Th = Wh + WPART;

        char* nbuf = sm2 + (b ^ 1) * BUF2_B;
        __nv_bfloat16* nWh = (__nv_bfloat16*)nbuf;
        __nv_bfloat16* nTh = nWh + WPART;

        const bool more = (dc + 1 < 16);
        if (more) {
            const int nd0 = (dc + 1) * 32;
            cp16(nWh + wrow * ST2 + wseg,     g_wh + wrow * D_ + nd0 + wseg);
            cp16(nWh + wrow * ST2 + wseg + 8, g_wh + wrow * D_ + nd0 + wseg + 8);
            CP_COMMIT();
            #pragma unroll
            for (int dd = 0; dd < 32; dd++) xr[dd] = xb[(size_t)(nd0 + dd) * P_];
        }

        // ---- MMA on current buffer (single bf16 pass) ----
        #pragma unroll
        for (int ks = 0; ks < 2; ks++) {
            const int kb = ks * 16;
            uint32_t Bh[4][2];
            #pragma unroll
            for (int t = 0; t < 4; t++) {
                int col = w * 32 + t * 8 + g;
                Bh[t][0] = *(const uint32_t*)(Th + col * ST2 + kb + tc * 2);
                Bh[t][1] = *(const uint32_t*)(Th + col * ST2 + kb + 8 + tc * 2);
            }
            #pragma unroll
            for (int mt = 0; mt < 4; mt++) {
                const int ar = mt * 16 + g;
                uint32_t Ah[4];
                Ah[0] = *(const uint32_t*)(Wh + ar * ST2 + kb + tc * 2);
                Ah[1] = *(const uint32_t*)(Wh + (ar + 8) * ST2 + kb + tc * 2);
                Ah[2] = *(const uint32_t*)(Wh + ar * ST2 + kb + 8 + tc * 2);
                Ah[3] = *(const uint32_t*)(Wh + (ar + 8) * ST2 + kb + 8 + tc * 2);
                #pragma unroll
                for (int t = 0; t < 4; t++)
                    mma_bf16(acc[mt][t], Ah, Bh[t]);
            }
        }

        if (more) {
            #pragma unroll
            for (int dd = 0; dd < 32; dd += 4) {
                float4 v = {xr[dd], xr[dd + 1], xr[dd + 2], xr[dd + 3]};
                ss += v.x * v.x + v.y * v.y + v.z * v.z + v.w * v.w;
                uint2 h; pack4h(v, h);
                *(uint2*)(nTh + tid * ST2 + dd) = h;
            }
            CP_WAIT0();
        }
        __syncthreads();
    }

    const float invnv = 1.0f / fmaxf(sqrtf(ss), EPSF);
    sInv[tid] = invnv;
    __syncthreads();

    // epilogue: scale by invn, stage logits into Ls (staging buffers dead now)
    #pragma unroll
    for (int mt = 0; mt < 4; mt++)
        #pragma unroll
        for (int t = 0; t < 4; t++) {
            int col = w * 32 + t * 8 + tc * 2;
            int row = mt * 16 + g;
            Ls[row * 132 + col]           = acc[mt][t][0] * sInv[col];
            Ls[row * 132 + col + 1]       = acc[mt][t][1] * sInv[col + 1];
            Ls[(row + 8) * 132 + col]     = acc[mt][t][2] * sInv[col];
            Ls[(row + 8) * 132 + col + 1] = acc[mt][t][3] * sInv[col + 1];
        }
    __syncthreads();

    // softmax over clusters; one thread per pixel column
    {
        float m = -1e30f;
        for (int k = 0; k < 64; k++) m = fmaxf(m, Ls[k * 132 + tid]);
        float s = 0.f;
        for (int k = 0; k < 64; k++) {
            float e = expf(Ls[k * 132 + tid] - m);
            Ls[k * 132 + tid] = e;
            s += e;
        }
        float inv = 1.0f / s;
        for (int k = 0; k < 64; k++) Ls[k * 132 + tid] *= inv;
    }
    __syncthreads();

    // write a_eff = a * invn, split bf16 hi/lo (k3 needs the split)
    {
        __nv_bfloat16* ah = g_ah + (size_t)n * K_ * P_ + p0 + tid;
        __nv_bfloat16* al = g_al + (size_t)n * K_ * P_ + p0 + tid;
        for (int k = 0; k < 64; k++) {
            float ae = Ls[k * 132 + tid] * invnv;
            float h = bf_hi(ae);
            ah[(size_t)k * P_] = __float2bfloat16_rn(ae);
            al[(size_t)k * P_] = __float2bfloat16_rn(ae - h);
        }
    }
    if (tid < 64) {
        float s = 0.f;
        for (int p = 0; p < 128; p++) s += Ls[tid * 132 + p];
        atomicAdd(&g_asum[n * K_ + tid], s);
    }
}

// ---------------- k3: vlad GEMM, double-buffered pipeline (3-term split) ----
#define ST3 136
#define XPART (128 * ST3)
#define APART (64 * ST3)
#define BUF_B ((2 * XPART + 2 * APART) * 2)   // 104448 bytes
#define K3_SMEM (2 * BUF_B)                    // 208896 bytes
#define NCH (P_ / 128)

__global__ __launch_bounds__(512) void k3_mma(const float* __restrict__ x) {
    extern __shared__ char sm3[];

    const int n  = blockIdx.y;
    const int d0 = blockIdx.x * 128;
    const int tid = threadIdx.x;
    const int w = tid >> 5, lane = tid & 31;
    const int g = lane >> 2, tc = lane & 3;
    const int mt = w >> 1;
    const int nh = (w & 1) * 32;

    const float* xn = x + (size_t)n * D_ * P_ + (size_t)d0 * P_;
    const __nv_bfloat16* gah = g_ah + (size_t)n * K_ * P_;
    const __nv_bfloat16* gal = g_al + (size_t)n * K_ * P_;

    float acc[4][4];
    #pragma unroll
    for (int t = 0; t < 4; t++)
        #pragma unroll
        for (int q = 0; q < 4; q++) acc[t][q] = 0.f;

    const int c4 = tid & 31;
    const int r0 = tid >> 5;

    float4 xv[8];

    // ---- prologue: stage chunk 0 into buffer 0 ----
    {
        char* buf = sm3;
        __nv_bfloat16* Xh = (__nv_bfloat16*)buf;
        __nv_bfloat16* Xl = Xh + XPART;
        __nv_bfloat16* Ahs = Xl + XPART;
        __nv_bfloat16* Als = Ahs + APART;
        #pragma unroll
        for (int j = 0; j < 2; j++) {
            int idx = tid + j * 512;
            int row = idx >> 4, seg = idx & 15;
            cp16(Ahs + row * ST3 + seg * 8, gah + (size_t)row * P_ + seg * 8);
            cp16(Als + row * ST3 + seg * 8, gal + (size_t)row * P_ + seg * 8);
        }
        CP_COMMIT();
        #pragma unroll
        for (int rr = 0; rr < 8; rr++)
            xv[rr] = *(const float4*)(xn + (size_t)(r0 + rr * 16) * P_ + c4 * 4);
        #pragma unroll
        for (int rr = 0; rr < 8; rr++) {
            int row = r0 + rr * 16;
            uint2 h, l; split4(xv[rr], h, l);
            *(uint2*)(Xh + row * ST3 + c4 * 4) = h;
            *(uint2*)(Xl + row * ST3 + c4 * 4) = l;
        }
        CP_WAIT0();
        __syncthreads();
    }

    for (int pc = 0; pc < NCH; pc++) {
        const int b = pc & 1;
        char* buf = sm3 + b * BUF_B;
        const __nv_bfloat16* Xh = (const __nv_bfloat16*)buf;
        const __nv_bfloat16* Xl = Xh + XPART;
        const __nv_bfloat16* Ahs = Xl + XPART;
        const __nv_bfloat16* Als = Ahs + APART;

        char* nbuf = sm3 + (b ^ 1) * BUF_B;
        __nv_bfloat16* nXh = (__nv_bfloat16*)nbuf;
        __nv_bfloat16* nXl = nXh + XPART;
        __nv_bfloat16* nAh = nXl + XPART;
        __nv_bfloat16* nAl = nAh + APART;

        const bool more = (pc + 1 < NCH);
        if (more) {
            const int pb = (pc + 1) * 128;
            #pragma unroll
            for (int j = 0; j < 2; j++) {
                int idx = tid + j * 512;
                int row = idx >> 4, seg = idx & 15;
                cp16(nAh + row * ST3 + seg * 8, gah + (size_t)row * P_ + pb + seg * 8);
                cp16(nAl + row * ST3 + seg * 8, gal + (size_t)row * P_ + pb + seg * 8);
            }
            CP_COMMIT();
            #pragma unroll
            for (int rr = 0; rr < 8; rr++)
                xv[rr] = *(const float4*)(xn + (size_t)(r0 + rr * 16) * P_ + pb + c4 * 4);
        }

        #pragma unroll
        for (int ks = 0; ks < 8; ks++) {
            const int kb = ks * 16;
            uint32_t Bh[4][2], Bl[4][2];
            #pragma unroll
            for (int t = 0; t < 4; t++) {
                int col = nh + t * 8 + g;
                Bh[t][0] = *(const uint32_t*)(Ahs + col * ST3 + kb + tc * 2);
                Bh[t][1] = *(const uint32_t*)(Ahs + col * ST3 + kb + 8 + tc * 2);
                Bl[t][0] = *(const uint32_t*)(Als + col * ST3 + kb + tc * 2);
                Bl[t][1] = *(const uint32_t*)(Als + col * ST3 + kb + 8 + tc * 2);
            }
            const int ar = mt * 16 + g;
            uint32_t Ah[4], Al[4];
            Ah[0] = *(const uint32_t*)(Xh + ar * ST3 + kb + tc * 2);
            Ah[1] = *(const uint32_t*)(Xh + (ar + 8) * ST3 + kb + tc * 2);
            Ah[2] = *(const uint32_t*)(Xh + ar * ST3 + kb + 8 + tc * 2);
            Ah[3] = *(const uint32_t*)(Xh + (ar + 8) * ST3 + kb + 8 + tc * 2);
            Al[0] = *(const uint32_t*)(Xl + ar * ST3 + kb + tc * 2);
            Al[1] = *(const uint32_t*)(Xl + (ar + 8) * ST3 + kb + tc * 2);
            Al[2] = *(const uint32_t*)(Xl + ar * ST3 + kb + 8 + tc * 2);
            Al[3] = *(const uint32_t*)(Xl + (ar + 8) * ST3 + kb + 8 + tc * 2);
            #pragma unroll
            for (int t = 0; t < 4; t++) {
                mma_bf16(acc[t], Ah, Bh[t]);
                mma_bf16(acc[t], Ah, Bl[t]);
                mma_bf16(acc[t], Al, Bh[t]);
            }
        }

        if (more) {
            #pragma unroll
            for (int rr = 0; rr < 8; rr++) {
                int row = r0 + rr * 16;
                uint2 h, l; split4(xv[rr], h, l);
                *(uint2*)(nXh + row * ST3 + c4 * 4) = h;
                *(uint2*)(nXl + row * ST3 + c4 * 4) = l;
            }
            CP_WAIT0();
        }
        __syncthreads();
    }

    float* vb = g_vlad + (size_t)n * K_ * D_ + d0;
    const int r = mt * 16 + g;
    #pragma unroll
    for (int t = 0; t < 4; t++) {
        int kc = nh + t * 8 + tc * 2;
        vb[(size_t)kc * D_ + r]           = acc[t][0];
        vb[(size_t)(kc + 1) * D_ + r]     = acc[t][1];
        vb[(size_t)kc * D_ + r + 8]       = acc[t][2];
        vb[(size_t)(kc + 1) * D_ + r + 8] = acc[t][3];
    }
}

// ---------------- k4a: centroid subtraction + intra-normalize -----------------
__global__ __launch_bounds__(128) void k4a_finalize(
        const float* __restrict__ cent, float* __restrict__ out) {
    const int k = blockIdx.x, n = blockIdx.y;
    const int tid = threadIdx.x;
    const float asum = g_asum[n * K_ + k];
    const float* vl = g_vlad + ((size_t)n * K_ + k) * D_;
    const float* ck = cent + (size_t)k * D_;

    float t[4];
    float s2 = 0.f;
    #pragma unroll
    for (int r = 0; r < 4; r++) {
        int d = r * 128 + tid;
        t[r] = vl[d] - asum * ck[d];
        s2 += t[r] * t[r];
    }
    #pragma unroll
    for (int o = 16; o > 0; o >>= 1) s2 += __shfl_xor_sync(0xffffffffu, s2, o);
    __shared__ float red[4];
    if ((tid & 31) == 0) red[tid >> 5] = s2;
    __syncthreads();
    float total = red[0] + red[1] + red[2] + red[3];
    float inv = 1.0f / fmaxf(sqrtf(total), EPSF);

    float* o = out + ((size_t)n * K_ + k) * D_;
    #pragma unroll
    for (int r = 0; r < 4; r++) o[r * 128 + tid] = t[r] * inv;
    if (tid == 0) atomicAdd(&g_gnorm2[n], total * inv * inv);
}

// ---------------- k4b: global L2 scale -----------------------------------------
__global__ void k4b_global(float* __restrict__ out) {
    int i = blockIdx.x * 256 + threadIdx.x;
    int n = i >> 15;
    float inv = 1.0f / fmaxf(sqrtf(g_gnorm2[n]), EPSF);
    out[i] *= inv;
}

// ---------------- launch --------------------------------------------------------
extern "C" void kernel_launch(void* const* d_in, const int* in_sizes, int n_in,
                              void* d_out, int out_size) {
    const float* x = (const float*)d_in[0];
    const float* w = (const float*)d_in[1];
    const float* c = (const float*)d_in[2];
    float* out = (float*)d_out;

    static bool attr_done = false;
    if (!attr_done) {
        cudaFuncSetAttribute(k2_mma, cudaFuncAttributeMaxDynamicSharedMemorySize, K2_SMEM);
        cudaFuncSetAttribute(k3_mma, cudaFuncAttributeMaxDynamicSharedMemorySize, K3_SMEM);
        attr_done = true;
    }

    k0_init<<<32, 256>>>(w);

    dim3 g2(P_ / 128, N_);
    k2_mma<<<g2, 128, K2_SMEM>>>(x);

    dim3 g3(D_ / 128, N_);
    k3_mma<<<g3, 512, K3_SMEM>>>(x);

    dim3 g4(K_, N_);
    k4a_finalize<<<g4, 128>>>(c, out);

    k4b_global<<<(N_ * K_ * D_) / 256, 256>>>(out);
}